// round 9
// baseline (speedup 1.0000x reference)
#include <cuda_runtime.h>
#include <cuda_bf16.h>

// DCN cross network, fused, affine-span form:
//   t_l = x0.w_l (4 dots, one reduction pass), beta_l = B_l.w_l (row-indep),
//   gamma recurrence, out = gamma4*x0 + Bsum.
// R8: R7 was issue-bound (46.7% issue, nothing saturated). Cuts:
//  - single gamma-warp: warp 0 computes cross-warp totals + gamma (overlapped
//    with other warps' shuffle chains pre-barrier), publishes one scalar;
//    other warps' epilogue = 1 LDS + 4 packed FMA + 2 STG.
//  - packed f32x2 dots/epilogue (sm_100a dual-issue FMA).
//  - 128-thread CTAs (4-warp barrier), R=8 rows, grid 2048, 6 CTAs/SM.

#define B_ROWS   16384
#define L_LAYERS 4
#define THREADS  128
#define VPR      256          // 16B vectors per row
#define R_ROWS   8            // grid = 2048

typedef unsigned long long u64;

__device__ __forceinline__ u64 fma2(u64 a, u64 b, u64 c) {
    u64 d; asm("fma.rn.f32x2 %0, %1, %2, %3;" : "=l"(d) : "l"(a), "l"(b), "l"(c)); return d;
}
__device__ __forceinline__ u64 mul2(u64 a, u64 b) {
    u64 d; asm("mul.rn.f32x2 %0, %1, %2;" : "=l"(d) : "l"(a), "l"(b)); return d;
}
__device__ __forceinline__ u64 add2(u64 a, u64 b) {
    u64 d; asm("add.rn.f32x2 %0, %1, %2;" : "=l"(d) : "l"(a), "l"(b)); return d;
}
__device__ __forceinline__ float hsum2(u64 p) {
    float lo, hi; asm("mov.b64 {%0, %1}, %2;" : "=f"(lo), "=f"(hi) : "l"(p)); return lo + hi;
}
__device__ __forceinline__ u64 pack2(float s) {
    u64 d; asm("mov.b64 %0, {%1, %1};" : "=l"(d) : "f"(s)); return d;
}
__device__ __forceinline__ ulonglong2 addv(ulonglong2 a, ulonglong2 b) {
    ulonglong2 r; r.x = add2(a.x, b.x); r.y = add2(a.y, b.y); return r;
}
// dot of this thread's 8 elems (two 16B vectors) against W slice
__device__ __forceinline__ float dotp(ulonglong2 a0, ulonglong2 a1,
                                      ulonglong2 w0, ulonglong2 w1) {
    u64 acc = mul2(a0.x, w0.x);
    acc = fma2(a0.y, w0.y, acc);
    acc = fma2(a1.x, w1.x, acc);
    acc = fma2(a1.y, w1.y, acc);
    return hsum2(acc);
}

__global__ __launch_bounds__(THREADS, 6)
void dcn_cross_kernel(const ulonglong2* __restrict__ x,
                      const ulonglong2* __restrict__ w,
                      const ulonglong2* __restrict__ b,
                      ulonglong2* __restrict__ out) {
    const int t    = threadIdx.x;      // 0..127
    const int lane = t & 31;
    const int wid  = t >> 5;           // 0..3

    __shared__ __align__(16) float4 sred[2][4];  // [r&1][warp] -> (t0..t3) partial
    __shared__ __align__(16) float4 sbeta[4];
    __shared__ float sg[2];                      // [r&1] -> gamma scalar

    // ---- W register-resident: 8 elems x 4 layers (packed) ----
    ulonglong2 W[L_LAYERS][2];
    #pragma unroll
    for (int l = 0; l < L_LAYERS; l++) {
        W[l][0] = w[l * VPR + t];
        W[l][1] = w[l * VPR + t + THREADS];
    }

    // ---- biases: Bsum slice + beta scalars ----
    ulonglong2 Bs0, Bs1;
    float p1, p2, p3;
    {
        Bs0 = b[0 * VPR + t]; Bs1 = b[0 * VPR + t + THREADS];      // B1
        p1 = dotp(Bs0, Bs1, W[1][0], W[1][1]);
        Bs0 = addv(Bs0, b[1 * VPR + t]); Bs1 = addv(Bs1, b[1 * VPR + t + THREADS]); // B2
        p2 = dotp(Bs0, Bs1, W[2][0], W[2][1]);
        Bs0 = addv(Bs0, b[2 * VPR + t]); Bs1 = addv(Bs1, b[2 * VPR + t + THREADS]); // B3
        p3 = dotp(Bs0, Bs1, W[3][0], W[3][1]);
        Bs0 = addv(Bs0, b[3 * VPR + t]); Bs1 = addv(Bs1, b[3 * VPR + t + THREADS]); // Bsum
    }
    #pragma unroll
    for (int o = 16; o > 0; o >>= 1) {
        p1 += __shfl_down_sync(0xffffffffu, p1, o);
        p2 += __shfl_down_sync(0xffffffffu, p2, o);
        p3 += __shfl_down_sync(0xffffffffu, p3, o);
    }
    if (lane == 0) sbeta[wid] = make_float4(p1, p2, p3, 0.f);
    __syncthreads();
    float beta1, beta2, beta3;
    {
        const float4 v0 = sbeta[0], v1 = sbeta[1], v2 = sbeta[2], v3 = sbeta[3];
        beta1 = (v0.x + v1.x) + (v2.x + v3.x);
        beta2 = (v0.y + v1.y) + (v2.y + v3.y);
        beta3 = (v0.z + v1.z) + (v2.z + v3.z);
    }

    // ---- pipelined row loop: one row per CTA in flight ----
    const size_t rowbase = (size_t)blockIdx.x * R_ROWS;
    const ulonglong2* xr = x + rowbase * VPR + t;
    ulonglong2* outr     = out + rowbase * VPR + t;

    ulonglong2 pf0 = __ldcs(&xr[0]), pf1 = __ldcs(&xr[THREADS]);
    ulonglong2 xp0, xp1;

    #pragma unroll 1
    for (int r = 0; r < R_ROWS; r++) {
        const ulonglong2 x0 = pf0, x1 = pf1;
        if (r + 1 < R_ROWS) {
            pf0 = __ldcs(&xr[(size_t)(r + 1) * VPR]);
            pf1 = __ldcs(&xr[(size_t)(r + 1) * VPR + THREADS]);
        }

        // 4 layer-dots (packed)
        float V0 = dotp(x0, x1, W[0][0], W[0][1]);
        float V1 = dotp(x0, x1, W[1][0], W[1][1]);
        float V2 = dotp(x0, x1, W[2][0], W[2][1]);
        float V3 = dotp(x0, x1, W[3][0], W[3][1]);

        // value-halving warp reduce: 6 SHFL, result idx = (lane>>3)&3
        {
            const bool hi16 = (lane & 16);
            float k0 = hi16 ? V2 : V0, g0 = hi16 ? V0 : V2;
            float k1 = hi16 ? V3 : V1, g1 = hi16 ? V1 : V3;
            V0 = k0 + __shfl_xor_sync(0xffffffffu, g0, 16);
            V1 = k1 + __shfl_xor_sync(0xffffffffu, g1, 16);
            const bool hi8 = (lane & 8);
            float k = hi8 ? V1 : V0, g = hi8 ? V0 : V1;
            V0 = k + __shfl_xor_sync(0xffffffffu, g, 8);
            V0 += __shfl_xor_sync(0xffffffffu, V0, 4);
            V0 += __shfl_xor_sync(0xffffffffu, V0, 2);
            V0 += __shfl_xor_sync(0xffffffffu, V0, 1);
        }
        if ((lane & 7) == 0)
            reinterpret_cast<float*>(&sred[r & 1][wid])[lane >> 3] = V0;

        // gamma-warp: compute row r-1's gamma before the barrier
        // (sred[(r-1)&1] written pre-barrier(r-1); rewrite only after bar(r))
        if (wid == 0 && r > 0) {
            const int pb = (r - 1) & 1;
            const float4 s0 = sred[pb][0], s1 = sred[pb][1];
            const float4 s2 = sred[pb][2], s3 = sred[pb][3];
            const float t0 = (s0.x + s1.x) + (s2.x + s3.x);
            const float t1 = (s0.y + s1.y) + (s2.y + s3.y);
            const float t2 = (s0.z + s1.z) + (s2.z + s3.z);
            const float t3 = (s0.w + s1.w) + (s2.w + s3.w);
            float g = 1.f + t0;
            g = fmaf(g, t1, g + beta1);
            g = fmaf(g, t2, g + beta2);
            g = fmaf(g, t3, g + beta3);
            if (lane == 0) sg[pb] = g;
        }
        __syncthreads();

        // deferred epilogue for row r-1: one scalar read + packed FMA
        if (r > 0) {
            const u64 gp = pack2(sg[(r - 1) & 1]);
            ulonglong2 o0, o1;
            o0.x = fma2(xp0.x, gp, Bs0.x); o0.y = fma2(xp0.y, gp, Bs0.y);
            o1.x = fma2(xp1.x, gp, Bs1.x); o1.y = fma2(xp1.y, gp, Bs1.y);
            __stcs(&outr[(size_t)(r - 1) * VPR], o0);
            __stcs(&outr[(size_t)(r - 1) * VPR + THREADS], o1);
        }
        xp0 = x0; xp1 = x1;
    }

    // tail: last row's gamma (partials already synced) + epilogue
    {
        const int pb = (R_ROWS - 1) & 1;
        const float4 s0 = sred[pb][0], s1 = sred[pb][1];
        const float4 s2 = sred[pb][2], s3 = sred[pb][3];
        const float t0 = (s0.x + s1.x) + (s2.x + s3.x);
        const float t1 = (s0.y + s1.y) + (s2.y + s3.y);
        const float t2 = (s0.z + s1.z) + (s2.z + s3.z);
        const float t3 = (s0.w + s1.w) + (s2.w + s3.w);
        float g = 1.f + t0;
        g = fmaf(g, t1, g + beta1);
        g = fmaf(g, t2, g + beta2);
        g = fmaf(g, t3, g + beta3);

        const u64 gp = pack2(g);
        ulonglong2 o0, o1;
        o0.x = fma2(xp0.x, gp, Bs0.x); o0.y = fma2(xp0.y, gp, Bs0.y);
        o1.x = fma2(xp1.x, gp, Bs1.x); o1.y = fma2(xp1.y, gp, Bs1.y);
        __stcs(&outr[(size_t)(R_ROWS - 1) * VPR], o0);
        __stcs(&outr[(size_t)(R_ROWS - 1) * VPR + THREADS], o1);
    }
}

extern "C" void kernel_launch(void* const* d_in, const int* in_sizes, int n_in,
                              void* d_out, int out_size) {
    const ulonglong2* x = (const ulonglong2*)d_in[0];
    const ulonglong2* w = (const ulonglong2*)d_in[1];
    const ulonglong2* b = (const ulonglong2*)d_in[2];
    ulonglong2* o = (ulonglong2*)d_out;
    dcn_cross_kernel<<<B_ROWS / R_ROWS, THREADS>>>(x, w, b, o);
}

// round 10
// speedup vs baseline: 1.1667x; 1.1667x over previous
#include <cuda_runtime.h>
#include <cuda_bf16.h>

// DCN cross network, fused, affine-span form:
//   t_l = x0.w_l (4 dots), beta_l = B_l.w_l (row-indep scalars),
//   gamma recurrence, out = gamma4*x0 + Bsum.
// R9: R8 was parallelism-starved (occ 30%, all pipes idle) on a
// barrier-per-row design. Now ONE WARP OWNS ONE ROW:
//  - warp-local butterfly reduction, zero barriers in the row path
//  - 8 LDG.128 in flight per thread per row (MLP 8, was 2)
//  - W + Bsum in shared (20KB/CTA, amortized over 16 rows); frees
//    32 regs -> 4 CTAs x 256 thr (32 warps/SM)
//  - interleaved slice v*32+lane: LDG coalesced, LDS conflict-free

#define B_ROWS   16384
#define THREADS  256
#define WARPS    8
#define RW       2            // rows per warp -> 16 rows/CTA, grid = 1024
#define VPR      256          // 16B vectors per row

typedef unsigned long long u64;

__device__ __forceinline__ u64 fma2(u64 a, u64 b, u64 c) {
    u64 d; asm("fma.rn.f32x2 %0, %1, %2, %3;" : "=l"(d) : "l"(a), "l"(b), "l"(c)); return d;
}
__device__ __forceinline__ u64 mul2(u64 a, u64 b) {
    u64 d; asm("mul.rn.f32x2 %0, %1, %2;" : "=l"(d) : "l"(a), "l"(b)); return d;
}
__device__ __forceinline__ u64 add2(u64 a, u64 b) {
    u64 d; asm("add.rn.f32x2 %0, %1, %2;" : "=l"(d) : "l"(a), "l"(b)); return d;
}
__device__ __forceinline__ float hsum2(u64 p) {
    float lo, hi; asm("mov.b64 {%0, %1}, %2;" : "=f"(lo), "=f"(hi) : "l"(p)); return lo + hi;
}
__device__ __forceinline__ u64 pack2(float s) {
    u64 d; asm("mov.b64 %0, {%1, %1};" : "=l"(d) : "f"(s)); return d;
}
__device__ __forceinline__ ulonglong2 addv(ulonglong2 a, ulonglong2 b) {
    ulonglong2 r; r.x = add2(a.x, b.x); r.y = add2(a.y, b.y); return r;
}
__device__ __forceinline__ float dotv(ulonglong2 a, ulonglong2 b) {
    return hsum2(fma2(a.y, b.y, mul2(a.x, b.x)));
}

__global__ __launch_bounds__(THREADS, 4)
void dcn_cross_kernel(const ulonglong2* __restrict__ x,
                      const ulonglong2* __restrict__ w,
                      const ulonglong2* __restrict__ b,
                      ulonglong2* __restrict__ out) {
    const int t    = threadIdx.x;
    const int lane = t & 31;
    const int wid  = t >> 5;

    __shared__ __align__(16) ulonglong2 sw[4][VPR];   // weights, 16KB
    __shared__ __align__(16) ulonglong2 sbsum[VPR];   // Bsum, 4KB
    __shared__ __align__(16) float4 sbeta[WARPS];

    // ---- prologue: stage W into smem, compute Bsum + betas ----
    {
        const ulonglong2 w0 = w[0 * VPR + t], w1 = w[1 * VPR + t];
        const ulonglong2 w2 = w[2 * VPR + t], w3 = w[3 * VPR + t];
        sw[0][t] = w0; sw[1][t] = w1; sw[2][t] = w2; sw[3][t] = w3;

        ulonglong2 B = b[0 * VPR + t];                 // B1
        float p1 = dotv(B, w1);
        B = addv(B, b[1 * VPR + t]);                   // B2
        float p2 = dotv(B, w2);
        B = addv(B, b[2 * VPR + t]);                   // B3
        float p3 = dotv(B, w3);
        B = addv(B, b[3 * VPR + t]);                   // Bsum
        sbsum[t] = B;

        #pragma unroll
        for (int o = 16; o > 0; o >>= 1) {
            p1 += __shfl_down_sync(0xffffffffu, p1, o);
            p2 += __shfl_down_sync(0xffffffffu, p2, o);
            p3 += __shfl_down_sync(0xffffffffu, p3, o);
        }
        if (lane == 0) sbeta[wid] = make_float4(p1, p2, p3, 0.f);
    }
    __syncthreads();

    float beta1 = 0.f, beta2 = 0.f, beta3 = 0.f;
    #pragma unroll
    for (int k = 0; k < WARPS; k++) {
        const float4 v = sbeta[k];
        beta1 += v.x; beta2 += v.y; beta3 += v.z;
    }

    // ---- row loop: one warp per row, no barriers ----
    #pragma unroll 1
    for (int r = 0; r < RW; r++) {
        const int row = blockIdx.x * (WARPS * RW) + wid + WARPS * r;
        const ulonglong2* xp = x + (size_t)row * VPR;
        ulonglong2* op       = out + (size_t)row * VPR;

        // 8 independent LDG.128 (MLP 8)
        ulonglong2 xr[8];
        #pragma unroll
        for (int v = 0; v < 8; v++)
            xr[v] = __ldcs(&xp[v * 32 + lane]);

        // 4 layer-dots against smem W (conflict-free LDS.128)
        float T0, T1, T2, T3;
        {
            u64 a0, a1, a2, a3;
            {
                const ulonglong2 wv = sw[0][lane];
                a0 = fma2(xr[0].y, wv.y, mul2(xr[0].x, wv.x));
            }
            {
                const ulonglong2 wv = sw[1][lane];
                a1 = fma2(xr[0].y, wv.y, mul2(xr[0].x, wv.x));
            }
            {
                const ulonglong2 wv = sw[2][lane];
                a2 = fma2(xr[0].y, wv.y, mul2(xr[0].x, wv.x));
            }
            {
                const ulonglong2 wv = sw[3][lane];
                a3 = fma2(xr[0].y, wv.y, mul2(xr[0].x, wv.x));
            }
            #pragma unroll
            for (int v = 1; v < 8; v++) {
                const ulonglong2 w0v = sw[0][v * 32 + lane];
                a0 = fma2(xr[v].x, w0v.x, a0); a0 = fma2(xr[v].y, w0v.y, a0);
                const ulonglong2 w1v = sw[1][v * 32 + lane];
                a1 = fma2(xr[v].x, w1v.x, a1); a1 = fma2(xr[v].y, w1v.y, a1);
                const ulonglong2 w2v = sw[2][v * 32 + lane];
                a2 = fma2(xr[v].x, w2v.x, a2); a2 = fma2(xr[v].y, w2v.y, a2);
                const ulonglong2 w3v = sw[3][v * 32 + lane];
                a3 = fma2(xr[v].x, w3v.x, a3); a3 = fma2(xr[v].y, w3v.y, a3);
            }
            T0 = hsum2(a0); T1 = hsum2(a1); T2 = hsum2(a2); T3 = hsum2(a3);
        }

        // warp-local butterfly: all lanes end with full-row totals
        #pragma unroll
        for (int o = 16; o > 0; o >>= 1) {
            T0 += __shfl_xor_sync(0xffffffffu, T0, o);
            T1 += __shfl_xor_sync(0xffffffffu, T1, o);
            T2 += __shfl_xor_sync(0xffffffffu, T2, o);
            T3 += __shfl_xor_sync(0xffffffffu, T3, o);
        }

        // gamma recurrence
        float g = 1.f + T0;
        g = fmaf(g, T1, g + beta1);
        g = fmaf(g, T2, g + beta2);
        g = fmaf(g, T3, g + beta3);
        const u64 gp = pack2(g);

        // epilogue: out = gamma*x0 + Bsum
        #pragma unroll
        for (int v = 0; v < 8; v++) {
            const ulonglong2 bs = sbsum[v * 32 + lane];
            ulonglong2 o2;
            o2.x = fma2(xr[v].x, gp, bs.x);
            o2.y = fma2(xr[v].y, gp, bs.y);
            __stcs(&op[v * 32 + lane], o2);
        }
    }
}

extern "C" void kernel_launch(void* const* d_in, const int* in_sizes, int n_in,
                              void* d_out, int out_size) {
    const ulonglong2* x = (const ulonglong2*)d_in[0];
    const ulonglong2* w = (const ulonglong2*)d_in[1];
    const ulonglong2* b = (const ulonglong2*)d_in[2];
    ulonglong2* o = (ulonglong2*)d_out;
    dcn_cross_kernel<<<B_ROWS / (WARPS * RW), THREADS>>>(x, w, b, o);
}

// round 12
// speedup vs baseline: 1.2383x; 1.0614x over previous
#include <cuda_runtime.h>
#include <cuda_bf16.h>

// DCN cross network, fused, affine-span form:
//   t_l = x0.w_l (4 dots), beta_l = B_l.w_l (row-indep), gamma recurrence,
//   out = gamma4*x0 + Bsum.
// R10: R9 was L1-bound (71%) on smem W re-reads (40 LDS/row/thread).
//  - each warp processes TWO rows at once: one W LDS feeds both rows'
//    FMAs -> W traffic per row halved (32 -> 16 LDS).
//  - Bsum lane-slice register-resident (loaded once/CTA): -8 LDS/row.
//  - value-halving reduce (6 SHFL) + 4 broadcasts = 10 SHFL/row (was 20).
//  - ~110 regs, (256,2): 16 warps/SM but 16 LDG.128 in flight per warp.

#define B_ROWS   16384
#define THREADS  256
#define WARPS    8
#define VPR      256          // 16B vectors per row

typedef unsigned long long u64;

__device__ __forceinline__ u64 fma2(u64 a, u64 b, u64 c) {
    u64 d; asm("fma.rn.f32x2 %0, %1, %2, %3;" : "=l"(d) : "l"(a), "l"(b), "l"(c)); return d;
}
__device__ __forceinline__ u64 mul2(u64 a, u64 b) {
    u64 d; asm("mul.rn.f32x2 %0, %1, %2;" : "=l"(d) : "l"(a), "l"(b)); return d;
}
__device__ __forceinline__ u64 add2(u64 a, u64 b) {
    u64 d; asm("add.rn.f32x2 %0, %1, %2;" : "=l"(d) : "l"(a), "l"(b)); return d;
}
__device__ __forceinline__ float hsum2(u64 p) {
    float lo, hi; asm("mov.b64 {%0, %1}, %2;" : "=f"(lo), "=f"(hi) : "l"(p)); return lo + hi;
}
__device__ __forceinline__ u64 pack2(float s) {
    u64 d; asm("mov.b64 %0, {%1, %1};" : "=l"(d) : "f"(s)); return d;
}
__device__ __forceinline__ ulonglong2 addv(ulonglong2 a, ulonglong2 b) {
    ulonglong2 r; r.x = add2(a.x, b.x); r.y = add2(a.y, b.y); return r;
}
__device__ __forceinline__ float dotv(ulonglong2 a, ulonglong2 b) {
    return hsum2(fma2(a.y, b.y, mul2(a.x, b.x)));
}

// reduce 4 values over the warp; returns (t0,t1,t2,t3) on all lanes. 10 SHFL.
__device__ __forceinline__ float4 wreduce4(float V0, float V1, float V2, float V3,
                                           int lane) {
    const bool hi16 = (lane & 16);
    float k0 = hi16 ? V2 : V0, g0 = hi16 ? V0 : V2;
    float k1 = hi16 ? V3 : V1, g1 = hi16 ? V1 : V3;
    float U0 = k0 + __shfl_xor_sync(0xffffffffu, g0, 16);
    float U1 = k1 + __shfl_xor_sync(0xffffffffu, g1, 16);
    const bool hi8 = (lane & 8);
    float k = hi8 ? U1 : U0, g = hi8 ? U0 : U1;
    float V = k + __shfl_xor_sync(0xffffffffu, g, 8);
    V += __shfl_xor_sync(0xffffffffu, V, 4);
    V += __shfl_xor_sync(0xffffffffu, V, 2);
    V += __shfl_xor_sync(0xffffffffu, V, 1);
    // lane group (lane>>3)&3 holds value idx; broadcast from lanes 0,8,16,24
    return make_float4(__shfl_sync(0xffffffffu, V, 0),
                       __shfl_sync(0xffffffffu, V, 8),
                       __shfl_sync(0xffffffffu, V, 16),
                       __shfl_sync(0xffffffffu, V, 24));
}

__global__ __launch_bounds__(THREADS, 2)
void dcn_cross_kernel(const ulonglong2* __restrict__ x,
                      const ulonglong2* __restrict__ w,
                      const ulonglong2* __restrict__ b,
                      ulonglong2* __restrict__ out) {
    const int t    = threadIdx.x;
    const int lane = t & 31;
    const int wid  = t >> 5;

    __shared__ __align__(16) ulonglong2 sw[4][VPR];   // weights, 16KB
    __shared__ __align__(16) ulonglong2 sbsum[VPR];   // Bsum, 4KB
    __shared__ __align__(16) float4 sbeta[WARPS];

    // ---- prologue: stage W, compute Bsum + beta scalars ----
    {
        const ulonglong2 w0 = w[0 * VPR + t], w1 = w[1 * VPR + t];
        const ulonglong2 w2 = w[2 * VPR + t], w3 = w[3 * VPR + t];
        sw[0][t] = w0; sw[1][t] = w1; sw[2][t] = w2; sw[3][t] = w3;

        ulonglong2 B = b[0 * VPR + t];                 // B1
        float p1 = dotv(B, w1);
        B = addv(B, b[1 * VPR + t]);                   // B2
        float p2 = dotv(B, w2);
        B = addv(B, b[2 * VPR + t]);                   // B3
        float p3 = dotv(B, w3);
        B = addv(B, b[3 * VPR + t]);                   // Bsum
        sbsum[t] = B;

        #pragma unroll
        for (int o = 16; o > 0; o >>= 1) {
            p1 += __shfl_down_sync(0xffffffffu, p1, o);
            p2 += __shfl_down_sync(0xffffffffu, p2, o);
            p3 += __shfl_down_sync(0xffffffffu, p3, o);
        }
        if (lane == 0) sbeta[wid] = make_float4(p1, p2, p3, 0.f);
    }
    __syncthreads();

    float beta1 = 0.f, beta2 = 0.f, beta3 = 0.f;
    #pragma unroll
    for (int k = 0; k < WARPS; k++) {
        const float4 v = sbeta[k];
        beta1 += v.x; beta2 += v.y; beta3 += v.z;
    }

    // Bsum lane-slice into registers (reused for both rows)
    ulonglong2 Bs[8];
    #pragma unroll
    for (int v = 0; v < 8; v++) Bs[v] = sbsum[v * 32 + lane];

    // ---- two rows per warp, processed jointly (shared W LDS) ----
    const int rowA = blockIdx.x * (WARPS * 2) + wid * 2;
    const ulonglong2* xpA = x + (size_t)rowA * VPR;
    const ulonglong2* xpB = xpA + VPR;
    ulonglong2* opA       = out + (size_t)rowA * VPR;
    ulonglong2* opB       = opA + VPR;

    ulonglong2 xA[8], xB[8];
    #pragma unroll
    for (int v = 0; v < 8; v++) xA[v] = __ldcs(&xpA[v * 32 + lane]);
    #pragma unroll
    for (int v = 0; v < 8; v++) xB[v] = __ldcs(&xpB[v * 32 + lane]);

    // dots: one W LDS serves both rows
    u64 aA[4], aB[4];
    #pragma unroll
    for (int l = 0; l < 4; l++) {
        const ulonglong2 wv = sw[l][lane];
        aA[l] = fma2(xA[0].y, wv.y, mul2(xA[0].x, wv.x));
        aB[l] = fma2(xB[0].y, wv.y, mul2(xB[0].x, wv.x));
    }
    #pragma unroll
    for (int v = 1; v < 8; v++) {
        #pragma unroll
        for (int l = 0; l < 4; l++) {
            const ulonglong2 wv = sw[l][v * 32 + lane];
            aA[l] = fma2(xA[v].x, wv.x, aA[l]);
            aA[l] = fma2(xA[v].y, wv.y, aA[l]);
            aB[l] = fma2(xB[v].x, wv.x, aB[l]);
            aB[l] = fma2(xB[v].y, wv.y, aB[l]);
        }
    }

    const float4 tA = wreduce4(hsum2(aA[0]), hsum2(aA[1]),
                               hsum2(aA[2]), hsum2(aA[3]), lane);
    const float4 tB = wreduce4(hsum2(aB[0]), hsum2(aB[1]),
                               hsum2(aB[2]), hsum2(aB[3]), lane);

    float gA = 1.f + tA.x;
    gA = fmaf(gA, tA.y, gA + beta1);
    gA = fmaf(gA, tA.z, gA + beta2);
    gA = fmaf(gA, tA.w, gA + beta3);
    float gB = 1.f + tB.x;
    gB = fmaf(gB, tB.y, gB + beta1);
    gB = fmaf(gB, tB.z, gB + beta2);
    gB = fmaf(gB, tB.w, gB + beta3);

    const u64 gpA = pack2(gA), gpB = pack2(gB);

    #pragma unroll
    for (int v = 0; v < 8; v++) {
        ulonglong2 oa, ob;
        oa.x = fma2(xA[v].x, gpA, Bs[v].x);
        oa.y = fma2(xA[v].y, gpA, Bs[v].y);
        ob.x = fma2(xB[v].x, gpB, Bs[v].x);
        ob.y = fma2(xB[v].y, gpB, Bs[v].y);
        __stcs(&opA[v * 32 + lane], oa);
        __stcs(&opB[v * 32 + lane], ob);
    }
}

extern "C" void kernel_launch(void* const* d_in, const int* in_sizes, int n_in,
                              void* d_out, int out_size) {
    const ulonglong2* x = (const ulonglong2*)d_in[0];
    const ulonglong2* w = (const ulonglong2*)d_in[1];
    const ulonglong2* b = (const ulonglong2*)d_in[2];
    ulonglong2* o = (ulonglong2*)d_out;
    dcn_cross_kernel<<<B_ROWS / (WARPS * 2), THREADS>>>(x, w, b, o);
}